// round 7
// baseline (speedup 1.0000x reference)
#include <cuda_runtime.h>
#include <cuda_bf16.h>
#include <cstdint>

// ============================================================================
// KoopmanOperator: z_{t+1} = z + DT*(z@A^T + sum_l a_l * U_l (V_l^T z))
// N=262144 rows, m=256, da=6, r=16, steps=8.
//
// mma.sync HMMA; z = fp32 D-fragment accumulator across all steps (identity
// exact). A-GEMM in bf16 (precision-critical). V-proj + U-GEMM in e4m3 fp8
// (low-rank term is ~1e-4 of z; fp8 rounding negligible) -> -21% LDS bytes
// and -21% tensor instructions vs all-bf16.
// Scales: V,U stored x64; pa packed with C1=1/16; output scaled C2=DT/256.
// C1*64*64*C2 = DT exactly (all powers of 2 except DT).
// ============================================================================

#define DT_C    0.1f
#define BMAX_C  0.3f
#define SCALE_W 64.0f
#define C1_PACK 0.0625f
#define C2_OUT  3.90625e-4f   /* DT/256 */

static constexpr int M_DIM  = 256;
static constexpr int TILE_M = 128;   // rows per CTA (8 warps x 16)

// Weight images (fragment-ordered):
//  BA  (bf16): DT*A, 512B units: [kc2 0..8)][nc 0..32)] -> 131072 B
//  BV8 (e4m3): 64*tanh(BV)*BMAX, 512B units: [chunk 0..8)][ncp 0..6)]
//              unit = {nc=2ncp: b0,b1; nc=2ncp+1: b0,b1}        -> 24576 B
//  BUA (e4m3): 64*tanh(BU)*BMAX, 512B units: [nc 0..32)]
//              unit = {chunk0: b0,b1; chunk1: b0,b1}            -> 16384 B
//  BUB (e4m3): 256B units: [nc 0..32)] unit = {chunk2: b0,b1}   ->  8192 B
static constexpr int BA_BYTES  = 8 * 32 * 512;   // 131072
static constexpr int BV8_BYTES = 8 * 6 * 512;    //  24576
static constexpr int BUA_BYTES = 32 * 512;       //  16384
static constexpr int BUB_BYTES = 32 * 256;       //   8192
static constexpr int O_BV8 = BA_BYTES;
static constexpr int O_BUA = O_BV8 + BV8_BYTES;
static constexpr int O_BUB = O_BUA + BUA_BYTES;
static constexpr int W_TOTAL = O_BUB + BUB_BYTES;  // 180224

__device__ __align__(16) unsigned char g_wfrag[W_TOTAL];

// ============================================================================
// helpers
// ============================================================================
__device__ __forceinline__ uint32_t smem_u32(const void* p) {
    uint32_t a;
    asm("{ .reg .u64 t; cvta.to.shared.u64 t, %1; cvt.u32.u64 %0, t; }"
        : "=r"(a) : "l"(p));
    return a;
}

// pack bf16x2: lo -> low 16 bits (first PTX src -> HIGH half).
__device__ __forceinline__ uint32_t packbf(float lo, float hi) {
    uint32_t r;
    asm("cvt.rn.satfinite.bf16x2.f32 %0, %1, %2;" : "=r"(r) : "f"(hi), "f"(lo));
    return r;
}
// pack e4m3x2 into u16: lo -> low byte.
__device__ __forceinline__ uint32_t packe4(float lo, float hi) {
    uint16_t r;
    asm("cvt.rn.satfinite.e4m3x2.f32 %0, %1, %2;" : "=h"(r) : "f"(hi), "f"(lo));
    return (uint32_t)r;
}

__device__ __forceinline__ void lds128(uint32_t& x, uint32_t& y,
                                       uint32_t& z, uint32_t& w, uint32_t addr) {
    asm volatile("ld.shared.v4.b32 {%0,%1,%2,%3}, [%4];"
                 : "=r"(x), "=r"(y), "=r"(z), "=r"(w) : "r"(addr));
}
__device__ __forceinline__ void lds64(uint32_t& x, uint32_t& y, uint32_t addr) {
    asm volatile("ld.shared.v2.b32 {%0,%1}, [%2];"
                 : "=r"(x), "=r"(y) : "r"(addr));
}

__device__ __forceinline__ void mma_bf16(float& d0, float& d1, float& d2, float& d3,
                                         uint32_t a0, uint32_t a1, uint32_t a2,
                                         uint32_t a3, uint32_t b0, uint32_t b1) {
    asm volatile(
        "mma.sync.aligned.m16n8k16.row.col.f32.bf16.bf16.f32 "
        "{%0,%1,%2,%3}, {%4,%5,%6,%7}, {%8,%9}, {%0,%1,%2,%3};"
        : "+f"(d0), "+f"(d1), "+f"(d2), "+f"(d3)
        : "r"(a0), "r"(a1), "r"(a2), "r"(a3), "r"(b0), "r"(b1));
}
__device__ __forceinline__ void mma_e4(float& d0, float& d1, float& d2, float& d3,
                                       uint32_t a0, uint32_t a1, uint32_t a2,
                                       uint32_t a3, uint32_t b0, uint32_t b1) {
    asm volatile(
        "mma.sync.aligned.m16n8k32.row.col.f32.e4m3.e4m3.f32 "
        "{%0,%1,%2,%3}, {%4,%5,%6,%7}, {%8,%9}, {%0,%1,%2,%3};"
        : "+f"(d0), "+f"(d1), "+f"(d2), "+f"(d3)
        : "r"(a0), "r"(a1), "r"(a2), "r"(a3), "r"(b0), "r"(b1));
}

// Gather one 16-col half of an fp8 A-fragment from packed pair registers.
// RA holds (for nc nA) per lane t: u32 = [pair(rows lg) | pair(rows lg+8)<<16],
// pair = 2 e4m3 bytes for cols {8*nA+2t, +1}. RB same for nc nB = nA+1.
// Output: alo = rows lg bytes [4t..4t+3] of the half; ahi = rows lg+8.
__device__ __forceinline__ void gather_half(uint32_t RA, uint32_t RB,
                                            uint32_t s0, uint32_t s1, bool selA,
                                            uint32_t& alo, uint32_t& ahi) {
    uint32_t A0 = __shfl_sync(0xFFFFFFFFu, RA, s0);
    uint32_t B0 = __shfl_sync(0xFFFFFFFFu, RB, s0);
    uint32_t A1 = __shfl_sync(0xFFFFFFFFu, RA, s1);
    uint32_t B1 = __shfl_sync(0xFFFFFFFFu, RB, s1);
    uint32_t S0 = selA ? A0 : B0;
    uint32_t S1 = selA ? A1 : B1;
    alo = __byte_perm(S0, S1, 0x5410);   // S0.b0,S0.b1,S1.b0,S1.b1
    ahi = __byte_perm(S0, S1, 0x7632);   // rows lg+8
}

// ============================================================================
// Precompute: build fragment-ordered weight images in g_wfrag.
// bf16 B-frag (m16n8k16 row.col): lane l: b0={B[k0][n],B[k0+1][n]},
//   b1={B[k0+8][n],B[k0+9][n]}; n=8nc+(l>>2), k0=16kc+(l&3)*2.
// e4m3 B-frag (m16n8k32 row.col): lane l: b0 bytes=B[kb..kb+3][n],
//   b1 bytes=B[kb+16..kb+19][n]; n=8nc+(l>>2), kb=32chunk+(l&3)*4.
// ============================================================================
__global__ void koop_pre(const float* __restrict__ A,
                         const float* __restrict__ BU,
                         const float* __restrict__ BV) {
    int id = blockIdx.x * blockDim.x + threadIdx.x;
    if (id >= W_TOTAL / 4) return;

    int r    = id & 3;
    int lane = (id >> 2) & 31;
    int tig = lane & 3, lg = lane >> 2;

    if (id < BA_BYTES / 4) {                       // --- BA: bf16 DT*A ---
        int rest = id >> 7;
        int nc = rest & 31, kc2 = rest >> 5;
        int kodd = r >> 1, breg = r & 1;
        int n  = 8 * nc + lg;
        int k0 = 16 * (2 * kc2 + kodd) + tig * 2 + breg * 8;
        reinterpret_cast<uint32_t*>(g_wfrag)[id] =
            packbf(DT_C * A[n * 256 + k0], DT_C * A[n * 256 + k0 + 1]);
        return;
    }

    float v[4];
    if (id < O_BUA / 4) {                          // --- BV8: e4m3 64*Vc ---
        int rest = (id - O_BV8 / 4) >> 7;
        int ncp = rest % 6, c = rest / 6;
        int nc = 2 * ncp + (r >> 1), breg = r & 1;
        int n  = 8 * nc + lg;
        int l_idx = n >> 4, r_idx = n & 15;
        int kb = 32 * c + breg * 16 + tig * 4;
#pragma unroll
        for (int q = 0; q < 4; q++)
            v[q] = tanhf(BV[(l_idx * 256 + kb + q) * 16 + r_idx]) * (BMAX_C * SCALE_W);
    } else if (id < O_BUB / 4) {                   // --- BUA: chunks 0,1 ---
        int nc = (id - O_BUA / 4) >> 7;
        int chunk = r >> 1, breg = r & 1;
        int n  = 8 * nc + lg;
        int kb = 32 * chunk + breg * 16 + tig * 4;
#pragma unroll
        for (int q = 0; q < 4; q++) {
            int k = kb + q, l_idx = k >> 4, r_idx = k & 15;
            v[q] = tanhf(BU[(l_idx * 256 + n) * 16 + r_idx]) * (BMAX_C * SCALE_W);
        }
    } else {                                       // --- BUB: chunk 2 ---
        int idb = id - O_BUB / 4;
        int breg = idb & 1;
        int lane2 = (idb >> 1) & 31;
        int nc = idb >> 6;
        int t2 = lane2 & 3, lg2 = lane2 >> 2;
        int n  = 8 * nc + lg2;
        int kb = 64 + breg * 16 + t2 * 4;
#pragma unroll
        for (int q = 0; q < 4; q++) {
            int k = kb + q, l_idx = k >> 4, r_idx = k & 15;
            v[q] = tanhf(BU[(l_idx * 256 + n) * 16 + r_idx]) * (BMAX_C * SCALE_W);
        }
    }
    reinterpret_cast<uint32_t*>(g_wfrag)[id] =
        packe4(v[0], v[1]) | (packe4(v[2], v[3]) << 16);
}

// ============================================================================
// Main persistent kernel: 256 threads (8 warps), each warp owns 16 rows.
// ============================================================================
__global__ void __launch_bounds__(256, 1)
koop_main(const float* __restrict__ z_in, const float* __restrict__ a_in,
          const int* __restrict__ steps_p, float* __restrict__ out, int n_tiles) {
    extern __shared__ unsigned char smem[];
    int tid = threadIdx.x, wid = tid >> 5, lane = tid & 31;
    int tig = lane & 3, lg = lane >> 2;

    {
        const uint4* src = reinterpret_cast<const uint4*>(g_wfrag);
        uint4* dst = reinterpret_cast<uint4*>(smem);
        for (int i = tid; i < W_TOTAL / 16; i += 256) dst[i] = src[i];
    }
    __syncthreads();

    const uint32_t sb   = smem_u32(smem);
    const uint32_t sbA  = sb + (uint32_t)lane * 16;
    const uint32_t sbV8 = sb + O_BV8 + (uint32_t)lane * 16;
    const uint32_t sbUA = sb + O_BUA + (uint32_t)lane * 16;
    const uint32_t sbUB = sb + O_BUB + (uint32_t)lane * 8;
    const int steps = steps_p ? *steps_p : 8;

    // shuffle source lanes for fp8 A-frag gather (constant per lane)
    const uint32_t qbase = (uint32_t)(lane & ~3);
    const uint32_t s0g = qbase + (uint32_t)((2 * tig) & 3);
    const uint32_t s1g = s0g + 1;
    const bool selA = tig < 2;

    for (int tile = blockIdx.x; tile < n_tiles; tile += gridDim.x) {
        int r0 = tile * TILE_M + wid * 16 + lg;
        const float2* zr0 = reinterpret_cast<const float2*>(z_in + (size_t)r0 * M_DIM);
        const float2* zr1 = reinterpret_cast<const float2*>(z_in + (size_t)(r0 + 8) * M_DIM);

        float acc[32][4];
#pragma unroll
        for (int nc = 0; nc < 32; nc++) {
            float2 v0 = zr0[4 * nc + tig];
            float2 v1 = zr1[4 * nc + tig];
            acc[nc][0] = v0.x; acc[nc][1] = v0.y;
            acc[nc][2] = v1.x; acc[nc][3] = v1.y;
        }
        float av0[6], av1[6];
#pragma unroll
        for (int l = 0; l < 6; l++) {
            av0[l] = a_in[(size_t)r0 * 6 + l] * C1_PACK;
            av1[l] = a_in[(size_t)(r0 + 8) * 6 + l] * C1_PACK;
        }

#pragma unroll 1
        for (int s = 0; s < steps; s++) {
            // ---- build fp8 A-frags of old z: afq8[chunk][a0..a3] ----
            uint32_t afq8[8][4];
#pragma unroll
            for (int c = 0; c < 8; c++) {
                uint32_t R[4];
#pragma unroll
                for (int j = 0; j < 4; j++) {
                    int n = 4 * c + j;
                    R[j] = packe4(acc[n][0], acc[n][1])
                         | (packe4(acc[n][2], acc[n][3]) << 16);
                }
                gather_half(R[0], R[1], s0g, s1g, selA, afq8[c][0], afq8[c][1]);
                gather_half(R[2], R[3], s0g, s1g, selA, afq8[c][2], afq8[c][3]);
            }

            // ---- V-proj (fp8): v' = z8 @ V'^T, pack pa pairs ----
            uint32_t paR[12];
#pragma unroll
            for (int ncp = 0; ncp < 6; ncp++) {
                float p0[4] = {0.f, 0.f, 0.f, 0.f};
                float p1[4] = {0.f, 0.f, 0.f, 0.f};
#pragma unroll
                for (int c = 0; c < 8; c++) {
                    uint32_t b0, b1, b2, b3;
                    lds128(b0, b1, b2, b3, sbV8 + (uint32_t)(c * 6 + ncp) * 512);
                    mma_e4(p0[0], p0[1], p0[2], p0[3],
                           afq8[c][0], afq8[c][1], afq8[c][2], afq8[c][3], b0, b1);
                    mma_e4(p1[0], p1[1], p1[2], p1[3],
                           afq8[c][0], afq8[c][1], afq8[c][2], afq8[c][3], b2, b3);
                }
                float sc0 = av0[ncp], sc1 = av1[ncp];
                paR[2 * ncp]     = packe4(p0[0] * sc0, p0[1] * sc0)
                                 | (packe4(p0[2] * sc1, p0[3] * sc1) << 16);
                paR[2 * ncp + 1] = packe4(p1[0] * sc0, p1[1] * sc0)
                                 | (packe4(p1[2] * sc1, p1[3] * sc1) << 16);
            }

            // ---- fp8 A-frags of pa: paq8[3][4] ----
            uint32_t paq8[3][4];
#pragma unroll
            for (int c = 0; c < 3; c++) {
                gather_half(paR[4 * c], paR[4 * c + 1], s0g, s1g, selA,
                            paq8[c][0], paq8[c][1]);
                gather_half(paR[4 * c + 2], paR[4 * c + 3], s0g, s1g, selA,
                            paq8[c][2], paq8[c][3]);
            }

            // ---- bf16 A-frags of old z (acc untouched so far) ----
            uint32_t af[16][4];
#pragma unroll
            for (int kc = 0; kc < 16; kc++) {
                af[kc][0] = packbf(acc[2 * kc][0],     acc[2 * kc][1]);
                af[kc][1] = packbf(acc[2 * kc][2],     acc[2 * kc][3]);
                af[kc][2] = packbf(acc[2 * kc + 1][0], acc[2 * kc + 1][1]);
                af[kc][3] = packbf(acc[2 * kc + 1][2], acc[2 * kc + 1][3]);
            }

            // ---- A-GEMM (bf16): acc += z @ (DT*A)^T ----
#pragma unroll
            for (int i = 0; i < 256; i++) {
                uint32_t b0, b1, b2, b3;
                lds128(b0, b1, b2, b3, sbA + (uint32_t)i * 512);
                int kc2 = i >> 5, nc = i & 31;
                mma_bf16(acc[nc][0], acc[nc][1], acc[nc][2], acc[nc][3],
                         af[2 * kc2][0], af[2 * kc2][1],
                         af[2 * kc2][2], af[2 * kc2][3], b0, b1);
                mma_bf16(acc[nc][0], acc[nc][1], acc[nc][2], acc[nc][3],
                         af[2 * kc2 + 1][0], af[2 * kc2 + 1][1],
                         af[2 * kc2 + 1][2], af[2 * kc2 + 1][3], b2, b3);
            }

            // ---- U-GEMM (fp8): acc += C2 * (pa8 @ U'^T) ----
#pragma unroll
            for (int nc = 0; nc < 32; nc++) {
                uint32_t u0, u1, u2, u3, u4, u5;
                lds128(u0, u1, u2, u3, sbUA + (uint32_t)nc * 512);
                lds64(u4, u5, sbUB + (uint32_t)nc * 256);
                float d0 = 0.f, d1 = 0.f, d2 = 0.f, d3 = 0.f;
                mma_e4(d0, d1, d2, d3,
                       paq8[0][0], paq8[0][1], paq8[0][2], paq8[0][3], u0, u1);
                mma_e4(d0, d1, d2, d3,
                       paq8[1][0], paq8[1][1], paq8[1][2], paq8[1][3], u2, u3);
                mma_e4(d0, d1, d2, d3,
                       paq8[2][0], paq8[2][1], paq8[2][2], paq8[2][3], u4, u5);
                acc[nc][0] += d0 * C2_OUT;
                acc[nc][1] += d1 * C2_OUT;
                acc[nc][2] += d2 * C2_OUT;
                acc[nc][3] += d3 * C2_OUT;
            }
        }

        // ---- store result ----
        float2* o0 = reinterpret_cast<float2*>(out + (size_t)r0 * M_DIM);
        float2* o1 = reinterpret_cast<float2*>(out + (size_t)(r0 + 8) * M_DIM);
#pragma unroll
        for (int nc = 0; nc < 32; nc++) {
            o0[4 * nc + tig] = make_float2(acc[nc][0], acc[nc][1]);
            o1[4 * nc + tig] = make_float2(acc[nc][2], acc[nc][3]);
        }
    }
}

// ============================================================================
// kernel_launch — graph-capturable: two kernel launches, no sync, no alloc.
// ============================================================================
extern "C" void kernel_launch(void* const* d_in, const int* in_sizes, int n_in,
                              void* d_out, int out_size) {
    const float* z  = (const float*)d_in[0];
    const float* a  = (const float*)d_in[1];
    const float* A  = (const float*)d_in[2];
    const float* BU = (const float*)d_in[3];
    const float* BV = (const float*)d_in[4];
    const int* steps = (n_in > 5) ? (const int*)d_in[5] : nullptr;

    int n_rows  = in_sizes[0] / M_DIM;
    int n_tiles = n_rows / TILE_M;

    cudaFuncSetAttribute(koop_main, cudaFuncAttributeMaxDynamicSharedMemorySize,
                         W_TOTAL);

    int pre_threads = W_TOTAL / 4;
    koop_pre<<<(pre_threads + 255) / 256, 256>>>(A, BU, BV);

    int dev = 0, sm_count = 0;
    cudaGetDevice(&dev);
    cudaDeviceGetAttribute(&sm_count, cudaDevAttrMultiProcessorCount, dev);
    if (sm_count <= 0) sm_count = 148;
    int grid = n_tiles < sm_count ? n_tiles : sm_count;

    koop_main<<<grid, 256, W_TOTAL>>>(z, a, steps, (float*)d_out, n_tiles);
}

// round 9
// speedup vs baseline: 4.4604x; 4.4604x over previous
#include <cuda_runtime.h>
#include <cuda_bf16.h>
#include <cstdint>

// ============================================================================
// KoopmanOperator: z_{t+1} = z + DT*(z@A^T + sum_l a_l * U_l (V_l^T z))
// N=262144 rows, m=256, da=6, r=16, steps=8.
//
// R9 (= R8 + batched precompute; R8 hit infra failure, never benched):
// algebraic step fusion. With X = I + dt*A (B = sum a_l U V^T is row-constant
// across steps):
//   z_out = (X + dt B)^P z ≈ X^P z + P*dt * (X^{P/2} U)(V^T X^{P-1-P/2}) z
// Centered powers cancel the first-order non-commutator residual; remaining
// error ~4dt^2[B,A]z ~1e-5 rel. Fused weights have the same shapes as
// single-step weights -> identical hot loop to the proven 1090us kernel,
// run once (steps=8 -> P=8, passes=1). Odd steps -> P=1 (exact R5 path).
// Hot loop: mma.sync bf16, z = fp32 D-fragment accumulator (identity exact).
// ============================================================================

#define DT_C    0.1f
#define BMAX_C  0.3f

static constexpr int M_DIM  = 256;
static constexpr int TILE_M = 128;   // rows per CTA (8 warps x 16)

// Fragment-ordered weight images (bf16), 512B frag-pair units:
//   BA: X^P - I   [kc2 0..8)][nc 0..32)] -> 131072 B
//   BV: Vhat      [kc2 0..8)][nc 0..12)] ->  49152 B
//   BU: P*dt*Uhat [kc2 0..3)][nc 0..32)] ->  49152 B
static constexpr int BA_BYTES = 8 * 32 * 512;
static constexpr int BV_BYTES = 8 * 12 * 512;
static constexpr int BU_BYTES = 3 * 32 * 512;
static constexpr int W_TOTAL  = BA_BYTES + BV_BYTES + BU_BYTES;  // 229376

__device__ __align__(16) unsigned char g_wfrag[W_TOTAL];

// fp32 precompute scratch
__device__ float g_X [65536];
__device__ float g_X2[65536];
__device__ float g_X3[65536];
__device__ float g_X4[65536];
__device__ float g_X8[65536];
__device__ float g_Um[24576];   // [m][lr]  U_c
__device__ float g_Vm[24576];   // [m][lr]  V_c
__device__ float g_Uh[24576];   // [m][lr]  X^{e1} * Um
__device__ float g_Vh[24576];   // [m][lr]  X^{e2,T} * Vm

__device__ __forceinline__ int pick_P(int steps) {
    if (steps > 0 && (steps % 8) == 0) return 8;
    if (steps > 0 && (steps % 4) == 0) return 4;
    if (steps > 0 && (steps % 2) == 0) return 2;
    return 1;
}

// ============================================================================
// helpers
// ============================================================================
__device__ __forceinline__ uint32_t smem_u32(const void* p) {
    uint32_t a;
    asm("{ .reg .u64 t; cvta.to.shared.u64 t, %1; cvt.u32.u64 %0, t; }"
        : "=r"(a) : "l"(p));
    return a;
}

// pack bf16x2: lo -> low 16 bits (first PTX src -> HIGH half).
__device__ __forceinline__ uint32_t packbf(float lo, float hi) {
    uint32_t r;
    asm("cvt.rn.satfinite.bf16x2.f32 %0, %1, %2;" : "=r"(r) : "f"(hi), "f"(lo));
    return r;
}

__device__ __forceinline__ void lds128(uint32_t& x, uint32_t& y,
                                       uint32_t& z, uint32_t& w, uint32_t addr) {
    asm volatile("ld.shared.v4.b32 {%0,%1,%2,%3}, [%4];"
                 : "=r"(x), "=r"(y), "=r"(z), "=r"(w) : "r"(addr));
}

__device__ __forceinline__ void mma_bf16(float& d0, float& d1, float& d2, float& d3,
                                         uint32_t a0, uint32_t a1, uint32_t a2,
                                         uint32_t a3, uint32_t b0, uint32_t b1) {
    asm volatile(
        "mma.sync.aligned.m16n8k16.row.col.f32.bf16.bf16.f32 "
        "{%0,%1,%2,%3}, {%4,%5,%6,%7}, {%8,%9}, {%0,%1,%2,%3};"
        : "+f"(d0), "+f"(d1), "+f"(d2), "+f"(d3)
        : "r"(a0), "r"(a1), "r"(a2), "r"(a3), "r"(b0), "r"(b1));
}

// ============================================================================
// Precompute stage 1: X = I + dt*A ; Um/Vm = tanh-clamped factors as [m][lr].
// ============================================================================
__global__ void koop_init(const float* __restrict__ A,
                          const float* __restrict__ BU,
                          const float* __restrict__ BV) {
    int id = blockIdx.x * blockDim.x + threadIdx.x;
    if (id < 65536) {
        int n = id >> 8, k = id & 255;
        g_X[id] = DT_C * A[id] + (n == k ? 1.f : 0.f);
    }
    if (id < 24576) {
        int m = id / 96, lr = id % 96, l = lr >> 4, ri = lr & 15;
        g_Um[id] = tanhf(BU[(l * 256 + m) * 16 + ri]) * BMAX_C;
        g_Vm[id] = tanhf(BV[(l * 256 + m) * 16 + ri]) * BMAX_C;
    }
}

// ============================================================================
// Precompute GEMMs: C[256,N] = op(A)[256,256] * B[256,N]. Tiled 64x64,
// 256 threads, 4x4 micro-tile. job = job_base + blockIdx.z so independent
// jobs batch into one launch. Roles resolved device-side (steps in dmem).
//  job 0: X2 = X*X     1: X3 = X2*X   2: X4 = X2*X2   3: X8 = X4*X4
//  job 4: Uh = E1*Um   (E1 = X^{P/2};      P=1 -> copy)
//  job 5: Vh = E2^T*Vm (E2 = X^{P-1-P/2};  P<=2 -> copy)
// ============================================================================
__global__ void koop_gemm(int job_base, const int* __restrict__ steps_p) {
    int job = job_base + (int)blockIdx.z;
    int steps = steps_p ? *steps_p : 8;
    int P = pick_P(steps);
    const float *Ap = nullptr, *Bp = nullptr;
    float* Cp = nullptr;
    int N = 256; bool tA = false, ident = false;
    if      (job == 0) { Ap = g_X;  Bp = g_X;  Cp = g_X2; }
    else if (job == 1) { Ap = g_X2; Bp = g_X;  Cp = g_X3; }
    else if (job == 2) { Ap = g_X2; Bp = g_X2; Cp = g_X4; }
    else if (job == 3) { Ap = g_X4; Bp = g_X4; Cp = g_X8; }
    else if (job == 4) {
        N = 96; Bp = g_Um; Cp = g_Uh;
        if (P == 8) Ap = g_X4; else if (P == 4) Ap = g_X2;
        else if (P == 2) Ap = g_X; else ident = true;
    } else {
        N = 96; Bp = g_Vm; Cp = g_Vh; tA = true;
        if (P == 8) Ap = g_X3; else if (P == 4) Ap = g_X;
        else ident = true;
    }

    int row0 = blockIdx.y * 64, col0 = blockIdx.x * 64;
    if (col0 >= N) return;
    int tx = threadIdx.x & 15, ty = threadIdx.x >> 4;

    if (ident) {
#pragma unroll
        for (int qi = 0; qi < 4; qi++)
#pragma unroll
            for (int qj = 0; qj < 4; qj++) {
                int rr = row0 + ty * 4 + qi, cc = col0 + tx * 4 + qj;
                if (cc < N) Cp[rr * N + cc] = Bp[rr * N + cc];
            }
        return;
    }

    __shared__ float As[16][64];
    __shared__ float Bs[16][68];
    float accv[4][4] = {};
    for (int k0 = 0; k0 < 256; k0 += 16) {
        for (int t = threadIdx.x; t < 1024; t += 256) {
            int kk = t >> 6, i = t & 63;
            As[kk][i] = tA ? Ap[(k0 + kk) * 256 + row0 + i]
                           : Ap[(row0 + i) * 256 + k0 + kk];
            int c = col0 + i;
            Bs[kk][i] = (c < N) ? Bp[(k0 + kk) * N + c] : 0.f;
        }
        __syncthreads();
#pragma unroll
        for (int kk = 0; kk < 16; kk++) {
            float a[4], b[4];
#pragma unroll
            for (int q = 0; q < 4; q++) { a[q] = As[kk][ty * 4 + q]; b[q] = Bs[kk][tx * 4 + q]; }
#pragma unroll
            for (int qi = 0; qi < 4; qi++)
#pragma unroll
                for (int qj = 0; qj < 4; qj++) accv[qi][qj] += a[qi] * b[qj];
        }
        __syncthreads();
    }
#pragma unroll
    for (int qi = 0; qi < 4; qi++)
#pragma unroll
        for (int qj = 0; qj < 4; qj++) {
            int cc = col0 + tx * 4 + qj;
            if (cc < N) Cp[(row0 + ty * 4 + qi) * N + cc] = accv[qi][qj];
        }
}

// ============================================================================
// Precompute stage 3: fragment images.
//  BA: W[n][k] = (X^P)[n][k] - I ;  BV: W[n=lr][k=m] = Vh[m][lr]
//  BU: W[n][k=lr] = P*dt * Uh[n][lr]
// bf16 B-frag (m16n8k16 row.col): lane l: b0={W[n][k0],W[n][k0+1]},
//   b1={W[n][k0+8],W[n][k0+9]}; n=8nc+(l>>2), k0=16kc+(l&3)*2.
// ============================================================================
__global__ void koop_frag(const int* __restrict__ steps_p) {
    int steps = steps_p ? *steps_p : 8;
    int P = pick_P(steps);
    const float* AP = (P == 8) ? g_X8 : (P == 4) ? g_X4 : (P == 2) ? g_X2 : g_X;
    float coefU = (float)P * DT_C;

    int id = blockIdx.x * blockDim.x + threadIdx.x;
    if (id >= W_TOTAL / 4) return;

    int r = id & 3, lane = (id >> 2) & 31, rest = id >> 7;
    int tig = lane & 3, lg = lane >> 2;
    int kodd = r >> 1, breg = r & 1;

    float lo, hi;
    if (id < BA_BYTES / 4) {
        int nc = rest & 31, kc2 = rest >> 5;
        int n  = 8 * nc + lg;
        int k0 = 16 * (2 * kc2 + kodd) + tig * 2 + breg * 8;
        lo = AP[n * 256 + k0]     - (n == k0     ? 1.f : 0.f);
        hi = AP[n * 256 + k0 + 1] - (n == k0 + 1 ? 1.f : 0.f);
    } else if (id < (BA_BYTES + BV_BYTES) / 4) {
        int rest2 = rest - (BA_BYTES / 512);
        int nc = rest2 % 12, kc2 = rest2 / 12;
        int n  = 8 * nc + lg;                      // lr index [0,96)
        int k0 = 16 * (2 * kc2 + kodd) + tig * 2 + breg * 8;
        lo = g_Vh[k0 * 96 + n];
        hi = g_Vh[(k0 + 1) * 96 + n];
    } else {
        int rest3 = rest - ((BA_BYTES + BV_BYTES) / 512);
        int nc = rest3 & 31, kc2 = rest3 >> 5;     // kc2 in [0,3)
        int n  = 8 * nc + lg;                      // output col [0,256)
        int k0 = 16 * (2 * kc2 + kodd) + tig * 2 + breg * 8;  // lr [0,96)
        lo = coefU * g_Uh[n * 96 + k0];
        hi = coefU * g_Uh[n * 96 + k0 + 1];
    }
    reinterpret_cast<uint32_t*>(g_wfrag)[id] = packbf(lo, hi);
}

// ============================================================================
// Main persistent kernel: 256 threads (8 warps), each warp owns 16 rows.
// Identical hot loop to the 1090us kernel, but passes = steps/P (8 -> 1).
// ============================================================================
__global__ void __launch_bounds__(256, 1)
koop_main(const float* __restrict__ z_in, const float* __restrict__ a_in,
          const int* __restrict__ steps_p, float* __restrict__ out, int n_tiles) {
    extern __shared__ unsigned char smem[];
    int tid = threadIdx.x, wid = tid >> 5, lane = tid & 31;
    int tig = lane & 3, lg = lane >> 2;

    {
        const uint4* src = reinterpret_cast<const uint4*>(g_wfrag);
        uint4* dst = reinterpret_cast<uint4*>(smem);
        for (int i = tid; i < W_TOTAL / 16; i += 256) dst[i] = src[i];
    }
    __syncthreads();

    const uint32_t sbA = smem_u32(smem) + (uint32_t)lane * 16;
    const uint32_t sbV = sbA + BA_BYTES;
    const uint32_t sbU = sbA + BA_BYTES + BV_BYTES;

    int steps = steps_p ? *steps_p : 8;
    int P = pick_P(steps);
    int passes = (steps > 0) ? steps / P : 0;

    for (int tile = blockIdx.x; tile < n_tiles; tile += gridDim.x) {
        int r0 = tile * TILE_M + wid * 16 + lg;
        const float2* zr0 = reinterpret_cast<const float2*>(z_in + (size_t)r0 * M_DIM);
        const float2* zr1 = reinterpret_cast<const float2*>(z_in + (size_t)(r0 + 8) * M_DIM);

        // acc = z in D-fragment layout: acc[nc] covers cols [8nc, 8nc+8);
        // [0],[1] = row r0 cols 8nc+2tig,+1 ; [2],[3] = row r0+8.
        float acc[32][4];
#pragma unroll
        for (int nc = 0; nc < 32; nc++) {
            float2 v0 = zr0[4 * nc + tig];
            float2 v1 = zr1[4 * nc + tig];
            acc[nc][0] = v0.x; acc[nc][1] = v0.y;
            acc[nc][2] = v1.x; acc[nc][3] = v1.y;
        }
        float av0[6], av1[6];
#pragma unroll
        for (int l = 0; l < 6; l++) {
            av0[l] = a_in[(size_t)r0 * 6 + l];
            av1[l] = a_in[(size_t)(r0 + 8) * 6 + l];
        }

#pragma unroll 1
        for (int s = 0; s < passes; s++) {
            // ---- snapshot old z as bf16 A-fragments ----
            uint32_t af[16][4];
#pragma unroll
            for (int kc = 0; kc < 16; kc++) {
                af[kc][0] = packbf(acc[2 * kc][0],     acc[2 * kc][1]);
                af[kc][1] = packbf(acc[2 * kc][2],     acc[2 * kc][3]);
                af[kc][2] = packbf(acc[2 * kc + 1][0], acc[2 * kc + 1][1]);
                af[kc][3] = packbf(acc[2 * kc + 1][2], acc[2 * kc + 1][3]);
            }

            // ---- A-GEMM: acc += z @ (X^P - I)^T  (N=256, K=256) ----
#pragma unroll
            for (int i = 0; i < 256; i++) {
                uint32_t b0, b1, b2, b3;
                lds128(b0, b1, b2, b3, sbA + (uint32_t)i * 512);
                int kc2 = i >> 5, nc = i & 31;
                mma_bf16(acc[nc][0], acc[nc][1], acc[nc][2], acc[nc][3],
                         af[2 * kc2][0], af[2 * kc2][1],
                         af[2 * kc2][2], af[2 * kc2][3], b0, b1);
                mma_bf16(acc[nc][0], acc[nc][1], acc[nc][2], acc[nc][3],
                         af[2 * kc2 + 1][0], af[2 * kc2 + 1][1],
                         af[2 * kc2 + 1][2], af[2 * kc2 + 1][3], b2, b3);
            }

            // ---- V-proj: proj = z @ Vhat^T (N=96), scale by a_l, pack ----
            uint32_t paf[6][4];
#pragma unroll
            for (int ncp = 0; ncp < 6; ncp++) {
                float p0[4] = {0.f, 0.f, 0.f, 0.f};
                float p1[4] = {0.f, 0.f, 0.f, 0.f};
#pragma unroll
                for (int kc2 = 0; kc2 < 8; kc2++) {
                    uint32_t b0, b1, b2, b3;
                    uint32_t base = sbV + (uint32_t)(kc2 * 12 + 2 * ncp) * 512;
                    lds128(b0, b1, b2, b3, base);
                    mma_bf16(p0[0], p0[1], p0[2], p0[3],
                             af[2 * kc2][0], af[2 * kc2][1],
                             af[2 * kc2][2], af[2 * kc2][3], b0, b1);
                    mma_bf16(p0[0], p0[1], p0[2], p0[3],
                             af[2 * kc2 + 1][0], af[2 * kc2 + 1][1],
                             af[2 * kc2 + 1][2], af[2 * kc2 + 1][3], b2, b3);
                    lds128(b0, b1, b2, b3, base + 512);
                    mma_bf16(p1[0], p1[1], p1[2], p1[3],
                             af[2 * kc2][0], af[2 * kc2][1],
                             af[2 * kc2][2], af[2 * kc2][3], b0, b1);
                    mma_bf16(p1[0], p1[1], p1[2], p1[3],
                             af[2 * kc2 + 1][0], af[2 * kc2 + 1][1],
                             af[2 * kc2 + 1][2], af[2 * kc2 + 1][3], b2, b3);
                }
                paf[ncp][0] = packbf(p0[0] * av0[ncp], p0[1] * av0[ncp]);
                paf[ncp][1] = packbf(p0[2] * av1[ncp], p0[3] * av1[ncp]);
                paf[ncp][2] = packbf(p1[0] * av0[ncp], p1[1] * av0[ncp]);
                paf[ncp][3] = packbf(p1[2] * av1[ncp], p1[3] * av1[ncp]);
            }

            // ---- U-GEMM: acc += pa @ (P*dt*Uhat)^T  (N=256, K=96) ----
#pragma unroll
            for (int i = 0; i < 96; i++) {
                uint32_t b0, b1, b2, b3;
                lds128(b0, b1, b2, b3, sbU + (uint32_t)i * 512);
                int kc2 = i >> 5, nc = i & 31;
                mma_bf16(acc[nc][0], acc[nc][1], acc[nc][2], acc[nc][3],
                         paf[2 * kc2][0], paf[2 * kc2][1],
                         paf[2 * kc2][2], paf[2 * kc2][3], b0, b1);
                mma_bf16(acc[nc][0], acc[nc][1], acc[nc][2], acc[nc][3],
                         paf[2 * kc2 + 1][0], paf[2 * kc2 + 1][1],
                         paf[2 * kc2 + 1][2], paf[2 * kc2 + 1][3], b2, b3);
            }
        }

        // ---- store result ----
        float2* o0 = reinterpret_cast<float2*>(out + (size_t)r0 * M_DIM);
        float2* o1 = reinterpret_cast<float2*>(out + (size_t)(r0 + 8) * M_DIM);
#pragma unroll
        for (int nc = 0; nc < 32; nc++) {
            o0[4 * nc + tig] = make_float2(acc[nc][0], acc[nc][1]);
            o1[4 * nc + tig] = make_float2(acc[nc][2], acc[nc][3]);
        }
    }
}

// ============================================================================
// kernel_launch — graph-capturable: kernel launches only, no sync, no alloc.
// ============================================================================
extern "C" void kernel_launch(void* const* d_in, const int* in_sizes, int n_in,
                              void* d_out, int out_size) {
    const float* z  = (const float*)d_in[0];
    const float* a  = (const float*)d_in[1];
    const float* A  = (const float*)d_in[2];
    const float* BU = (const float*)d_in[3];
    const float* BV = (const float*)d_in[4];
    const int* steps = (n_in > 5) ? (const int*)d_in[5] : nullptr;

    int n_rows  = in_sizes[0] / M_DIM;
    int n_tiles = n_rows / TILE_M;

    cudaFuncSetAttribute(koop_main, cudaFuncAttributeMaxDynamicSharedMemorySize,
                         W_TOTAL);

    // Precompute chain, batched by dependency level:
    //   init -> X2 -> {X3, X4} -> {X8, Uh, Vh} -> frag
    koop_init<<<256, 256>>>(A, BU, BV);
    koop_gemm<<<dim3(4, 4, 1), 256>>>(0, steps);   // X2
    koop_gemm<<<dim3(4, 4, 2), 256>>>(1, steps);   // X3, X4
    koop_gemm<<<dim3(4, 4, 3), 256>>>(3, steps);   // X8, Uh, Vh
    koop_frag<<<(W_TOTAL / 4 + 255) / 256, 256>>>(steps);

    int dev = 0, sm_count = 0;
    cudaGetDevice(&dev);
    cudaDeviceGetAttribute(&sm_count, cudaDevAttrMultiProcessorCount, dev);
    if (sm_count <= 0) sm_count = 148;
    int grid = n_tiles < sm_count ? n_tiles : sm_count;

    koop_main<<<grid, 256, W_TOTAL>>>(z, a, steps, (float*)d_out, n_tiles);
}

// round 12
// speedup vs baseline: 5.7016x; 1.2783x over previous
#include <cuda_runtime.h>
#include <cuda_bf16.h>
#include <cstdint>

// ============================================================================
// KoopmanOperator: z_{t+1} = z + DT*(z@A^T + sum_l a_l * U_l (V_l^T z))
// N=262144 rows, m=256, da=6, r=16, steps=8.
//
// R11 = R10 resubmitted verbatim (R10 hit "container failed twice" infra,
// never benched). R9 baseline: 325us with ~140us of that in three ~47us
// latency-bound precompute GEMM launches (grid=48, occ 12%, DRAM 0.2%).
//
// R10/R11 changes vs R9:
//  * X^3 eliminated: Vh = X^T (X2^T V) -> 3 (not 4) 256^3 GEMMs + 2 thin ones
//  * precompute GEMM rebuilt: 32x32 tiles, 64-192 CTAs/launch, 256 thr,
//    2x2 micro-tile, double-buffered SMEM, float4 global loads
// Hot kernel identical to R9 (mma.sync bf16 fused-operator single pass,
// z = fp32 D-fragment accumulator; steps=8 -> P=8, passes=1).
// ============================================================================

#define DT_C    0.1f
#define BMAX_C  0.3f

static constexpr int M_DIM  = 256;
static constexpr int TILE_M = 128;   // rows per CTA (8 warps x 16)

// Fragment-ordered weight images (bf16), 512B frag-pair units:
//   BA: X^P - I   [kc2 0..8)][nc 0..32)] -> 131072 B
//   BV: Vhat      [kc2 0..8)][nc 0..12)] ->  49152 B
//   BU: P*dt*Uhat [kc2 0..3)][nc 0..32)] ->  49152 B
static constexpr int BA_BYTES = 8 * 32 * 512;
static constexpr int BV_BYTES = 8 * 12 * 512;
static constexpr int BU_BYTES = 3 * 32 * 512;
static constexpr int W_TOTAL  = BA_BYTES + BV_BYTES + BU_BYTES;  // 229376

__device__ __align__(16) unsigned char g_wfrag[W_TOTAL];

// fp32 precompute scratch
__device__ __align__(16) float g_X [65536];
__device__ __align__(16) float g_X2[65536];
__device__ __align__(16) float g_X4[65536];
__device__ __align__(16) float g_X8[65536];
__device__ __align__(16) float g_Um[24576];   // [m][lr]
__device__ __align__(16) float g_Vm[24576];   // [m][lr]
__device__ __align__(16) float g_T [24576];   // [m][lr]  X2^T * Vm (P=8)
__device__ __align__(16) float g_Uh[24576];   // [m][lr]  E1 * Um
__device__ __align__(16) float g_Vh[24576];   // [m][lr]  E2^T * Vm

__device__ __forceinline__ int pick_P(int steps) {
    if (steps > 0 && (steps % 8) == 0) return 8;
    if (steps > 0 && (steps % 4) == 0) return 4;
    if (steps > 0 && (steps % 2) == 0) return 2;
    return 1;
}

// ============================================================================
// helpers
// ============================================================================
__device__ __forceinline__ uint32_t smem_u32(const void* p) {
    uint32_t a;
    asm("{ .reg .u64 t; cvta.to.shared.u64 t, %1; cvt.u32.u64 %0, t; }"
        : "=r"(a) : "l"(p));
    return a;
}

// pack bf16x2: lo -> low 16 bits (first PTX src -> HIGH half).
__device__ __forceinline__ uint32_t packbf(float lo, float hi) {
    uint32_t r;
    asm("cvt.rn.satfinite.bf16x2.f32 %0, %1, %2;" : "=r"(r) : "f"(hi), "f"(lo));
    return r;
}

__device__ __forceinline__ void lds128(uint32_t& x, uint32_t& y,
                                       uint32_t& z, uint32_t& w, uint32_t addr) {
    asm volatile("ld.shared.v4.b32 {%0,%1,%2,%3}, [%4];"
                 : "=r"(x), "=r"(y), "=r"(z), "=r"(w) : "r"(addr));
}

__device__ __forceinline__ void mma_bf16(float& d0, float& d1, float& d2, float& d3,
                                         uint32_t a0, uint32_t a1, uint32_t a2,
                                         uint32_t a3, uint32_t b0, uint32_t b1) {
    asm volatile(
        "mma.sync.aligned.m16n8k16.row.col.f32.bf16.bf16.f32 "
        "{%0,%1,%2,%3}, {%4,%5,%6,%7}, {%8,%9}, {%0,%1,%2,%3};"
        : "+f"(d0), "+f"(d1), "+f"(d2), "+f"(d3)
        : "r"(a0), "r"(a1), "r"(a2), "r"(a3), "r"(b0), "r"(b1));
}

// ============================================================================
// Precompute stage 1: X = I + dt*A ; Um/Vm as [m][lr].
// ============================================================================
__global__ void koop_init(const float* __restrict__ A,
                          const float* __restrict__ BU,
                          const float* __restrict__ BV) {
    int id = blockIdx.x * blockDim.x + threadIdx.x;
    if (id < 65536) {
        int n = id >> 8, k = id & 255;
        g_X[id] = DT_C * A[id] + (n == k ? 1.f : 0.f);
    }
    if (id < 24576) {
        int m = id / 96, lr = id % 96, l = lr >> 4, ri = lr & 15;
        g_Um[id] = tanhf(BU[(l * 256 + m) * 16 + ri]) * BMAX_C;
        g_Vm[id] = tanhf(BV[(l * 256 + m) * 16 + ri]) * BMAX_C;
    }
}

// ============================================================================
// Fast precompute GEMM: C[256,N] = op(A)[256,256] * B[256,N].
// 32x32 tiles, 256 threads (2x2 micro), k-chunk 32, double-buffered SMEM,
// float4 global loads. job = job_base + blockIdx.z (independent jobs batch).
//  0: X2 = X*X
//  1: X4 = X2*X2           2: T  = X2^T*Vm (P=8) | copy Vm (P<8)    [N=96]
//  3: X8 = X4*X4           4: Uh = E1*Um | copy  (E1 = X^{P/2})     [N=96]
//                          5: Vh = X^T*T (P>=4) | copy T            [N=96]
// All N=96 jobs have full 32-wide tiles (96 = 3*32): no partial tiles.
// ============================================================================
__global__ void __launch_bounds__(256, 1)
koop_gemm2(int job_base, const int* __restrict__ steps_p) {
    int job = job_base + (int)blockIdx.z;
    int steps = steps_p ? *steps_p : 8;
    int P = pick_P(steps);
    const float *Ap = nullptr, *Bp = nullptr;
    float* Cp = nullptr;
    int N = 256; bool tA = false, ident = false;
    switch (job) {
    case 0: Ap = g_X;  Bp = g_X;  Cp = g_X2; break;
    case 1: Ap = g_X2; Bp = g_X2; Cp = g_X4; break;
    case 2: N = 96; Bp = g_Vm; Cp = g_T; tA = true;
            if (P == 8) Ap = g_X2; else ident = true; break;
    case 3: Ap = g_X4; Bp = g_X4; Cp = g_X8; break;
    case 4: N = 96; Bp = g_Um; Cp = g_Uh;
            if (P == 8) Ap = g_X4; else if (P == 4) Ap = g_X2;
            else if (P == 2) Ap = g_X; else ident = true; break;
    default: N = 96; Bp = g_T; Cp = g_Vh; tA = true;
            if (P >= 4) Ap = g_X; else ident = true; break;
    }

    int row0 = blockIdx.y * 32, col0 = blockIdx.x * 32;
    if (col0 >= N) return;
    int tid = threadIdx.x;

    if (ident) {
        for (int q = tid; q < 32 * 32; q += 256) {
            int i = q >> 5, j = q & 31;
            Cp[(row0 + i) * N + col0 + j] = Bp[(row0 + i) * N + col0 + j];
        }
        return;
    }

    __shared__ float As[2][32][33];
    __shared__ float Bs[2][32][33];
    int tx = tid & 15, ty = tid >> 4;
    float c00 = 0.f, c01 = 0.f, c10 = 0.f, c11 = 0.f;

    int q = tid * 4;
    int qhi = q >> 5, qlo = q & 31;     // each thread owns one float4 per tile

    // prologue load chunk 0 into buf 0
    {
        if (!tA) {      // As[kk..kk+3][i] from A[row0+i][0+kk..]
            float4 v = *reinterpret_cast<const float4*>(Ap + (row0 + qhi) * 256 + qlo);
            As[0][qlo][qhi] = v.x; As[0][qlo + 1][qhi] = v.y;
            As[0][qlo + 2][qhi] = v.z; As[0][qlo + 3][qhi] = v.w;
        } else {        // As[kk][i..i+3] from A[0+kk][row0+i..]
            float4 v = *reinterpret_cast<const float4*>(Ap + qhi * 256 + row0 + qlo);
            As[0][qhi][qlo] = v.x; As[0][qhi][qlo + 1] = v.y;
            As[0][qhi][qlo + 2] = v.z; As[0][qhi][qlo + 3] = v.w;
        }
        float4 v = *reinterpret_cast<const float4*>(Bp + qhi * N + col0 + qlo);
        Bs[0][qhi][qlo] = v.x; Bs[0][qhi][qlo + 1] = v.y;
        Bs[0][qhi][qlo + 2] = v.z; Bs[0][qhi][qlo + 3] = v.w;
    }
    __syncthreads();

#pragma unroll
    for (int kc = 0; kc < 8; kc++) {
        int b = kc & 1;
        if (kc + 1 < 8) {
            int k0 = (kc + 1) * 32, nb = b ^ 1;
            if (!tA) {
                float4 v = *reinterpret_cast<const float4*>(
                    Ap + (row0 + qhi) * 256 + k0 + qlo);
                As[nb][qlo][qhi] = v.x; As[nb][qlo + 1][qhi] = v.y;
                As[nb][qlo + 2][qhi] = v.z; As[nb][qlo + 3][qhi] = v.w;
            } else {
                float4 v = *reinterpret_cast<const float4*>(
                    Ap + (k0 + qhi) * 256 + row0 + qlo);
                As[nb][qhi][qlo] = v.x; As[nb][qhi][qlo + 1] = v.y;
                As[nb][qhi][qlo + 2] = v.z; As[nb][qhi][qlo + 3] = v.w;
            }
            float4 v = *reinterpret_cast<const float4*>(
                Bp + (k0 + qhi) * N + col0 + qlo);
            Bs[nb][qhi][qlo] = v.x; Bs[nb][qhi][qlo + 1] = v.y;
            Bs[nb][qhi][qlo + 2] = v.z; Bs[nb][qhi][qlo + 3] = v.w;
        }
#pragma unroll
        for (int kk = 0; kk < 32; kk++) {
            float a0 = As[b][kk][ty * 2], a1 = As[b][kk][ty * 2 + 1];
            float b0 = Bs[b][kk][tx * 2], b1 = Bs[b][kk][tx * 2 + 1];
            c00 += a0 * b0; c01 += a0 * b1;
            c10 += a1 * b0; c11 += a1 * b1;
        }
        __syncthreads();
    }

    int rr = row0 + ty * 2, cc = col0 + tx * 2;
    Cp[rr * N + cc] = c00;       Cp[rr * N + cc + 1] = c01;
    Cp[(rr + 1) * N + cc] = c10; Cp[(rr + 1) * N + cc + 1] = c11;
}

// ============================================================================
// Precompute stage 3: fragment images.
//  BA: W[n][k] = (X^P)[n][k] - I ;  BV: W[n=lr][k=m] = Vh[m][lr]
//  BU: W[n][k=lr] = P*dt * Uh[n][lr]
// bf16 B-frag (m16n8k16 row.col): lane l: b0={W[n][k0],W[n][k0+1]},
//   b1={W[n][k0+8],W[n][k0+9]}; n=8nc+(l>>2), k0=16kc+(l&3)*2.
// ============================================================================
__global__ void koop_frag(const int* __restrict__ steps_p) {
    int steps = steps_p ? *steps_p : 8;
    int P = pick_P(steps);
    const float* AP = (P == 8) ? g_X8 : (P == 4) ? g_X4 : (P == 2) ? g_X2 : g_X;
    float coefU = (float)P * DT_C;

    int id = blockIdx.x * blockDim.x + threadIdx.x;
    if (id >= W_TOTAL / 4) return;

    int r = id & 3, lane = (id >> 2) & 31, rest = id >> 7;
    int tig = lane & 3, lg = lane >> 2;
    int kodd = r >> 1, breg = r & 1;

    float lo, hi;
    if (id < BA_BYTES / 4) {
        int nc = rest & 31, kc2 = rest >> 5;
        int n  = 8 * nc + lg;
        int k0 = 16 * (2 * kc2 + kodd) + tig * 2 + breg * 8;
        lo = AP[n * 256 + k0]     - (n == k0     ? 1.f : 0.f);
        hi = AP[n * 256 + k0 + 1] - (n == k0 + 1 ? 1.f : 0.f);
    } else if (id < (BA_BYTES + BV_BYTES) / 4) {
        int rest2 = rest - (BA_BYTES / 512);
        int nc = rest2 % 12, kc2 = rest2 / 12;
        int n  = 8 * nc + lg;                      // lr index [0,96)
        int k0 = 16 * (2 * kc2 + kodd) + tig * 2 + breg * 8;
        lo = g_Vh[k0 * 96 + n];
        hi = g_Vh[(k0 + 1) * 96 + n];
    } else {
        int rest3 = rest - ((BA_BYTES + BV_BYTES) / 512);
        int nc = rest3 & 31, kc2 = rest3 >> 5;     // kc2 in [0,3)
        int n  = 8 * nc + lg;                      // output col [0,256)
        int k0 = 16 * (2 * kc2 + kodd) + tig * 2 + breg * 8;  // lr [0,96)
        lo = coefU * g_Uh[n * 96 + k0];
        hi = coefU * g_Uh[n * 96 + k0 + 1];
    }
    reinterpret_cast<uint32_t*>(g_wfrag)[id] = packbf(lo, hi);
}

// ============================================================================
// Main persistent kernel (unchanged from R9): 256 threads, 8 warps x 16 rows,
// passes = steps/P (8 -> 1 pass).
// ============================================================================
__global__ void __launch_bounds__(256, 1)
koop_main(const float* __restrict__ z_in, const float* __restrict__ a_in,
          const int* __restrict__ steps_p, float* __restrict__ out, int n_tiles) {
    extern __shared__ unsigned char smem[];
    int tid = threadIdx.x, wid = tid >> 5, lane = tid & 31;
    int tig = lane & 3, lg = lane >> 2;

    {
        const uint4* src = reinterpret_cast<const uint4*>(g_wfrag);
        uint4* dst = reinterpret_cast<uint4*>(smem);
        for (int i = tid; i < W_TOTAL / 16; i += 256) dst[i] = src[i];
    }
    __syncthreads();

    const uint32_t sbA = smem_u32(smem) + (uint32_t)lane * 16;
    const uint32_t sbV = sbA + BA_BYTES;
    const uint32_t sbU = sbA + BA_BYTES + BV_BYTES;

    int steps = steps_p ? *steps_p : 8;
    int P = pick_P(steps);
    int passes = (steps > 0) ? steps / P : 0;

    for (int tile = blockIdx.x; tile < n_tiles; tile += gridDim.x) {
        int r0 = tile * TILE_M + wid * 16 + lg;
        const float2* zr0 = reinterpret_cast<const float2*>(z_in + (size_t)r0 * M_DIM);
        const float2* zr1 = reinterpret_cast<const float2*>(z_in + (size_t)(r0 + 8) * M_DIM);

        float acc[32][4];
#pragma unroll
        for (int nc = 0; nc < 32; nc++) {
            float2 v0 = zr0[4 * nc + tig];
            float2 v1 = zr1[4 * nc + tig];
            acc[nc][0] = v0.x; acc[nc][1] = v0.y;
            acc[nc][2] = v1.x; acc[nc][3] = v1.y;
        }
        float av0[6], av1[6];
#pragma unroll
        for (int l = 0; l < 6; l++) {
            av0[l] = a_in[(size_t)r0 * 6 + l];
            av1[l] = a_in[(size_t)(r0 + 8) * 6 + l];
        }

#pragma unroll 1
        for (int s = 0; s < passes; s++) {
            uint32_t af[16][4];
#pragma unroll
            for (int kc = 0; kc < 16; kc++) {
                af[kc][0] = packbf(acc[2 * kc][0],     acc[2 * kc][1]);
                af[kc][1] = packbf(acc[2 * kc][2],     acc[2 * kc][3]);
                af[kc][2] = packbf(acc[2 * kc + 1][0], acc[2 * kc + 1][1]);
                af[kc][3] = packbf(acc[2 * kc + 1][2], acc[2 * kc + 1][3]);
            }

            // ---- A-GEMM: acc += z @ (X^P - I)^T ----
#pragma unroll
            for (int i = 0; i < 256; i++) {
                uint32_t b0, b1, b2, b3;
                lds128(b0, b1, b2, b3, sbA + (uint32_t)i * 512);
                int kc2 = i >> 5, nc = i & 31;
                mma_bf16(acc[nc][0], acc[nc][1], acc[nc][2], acc[nc][3],
                         af[2 * kc2][0], af[2 * kc2][1],
                         af[2 * kc2][2], af[2 * kc2][3], b0, b1);
                mma_bf16(acc[nc][0], acc[nc][1], acc[nc][2], acc[nc][3],
                         af[2 * kc2 + 1][0], af[2 * kc2 + 1][1],
                         af[2 * kc2 + 1][2], af[2 * kc2 + 1][3], b2, b3);
            }

            // ---- V-proj: proj = z @ Vhat^T (N=96), scale by a_l, pack ----
            uint32_t paf[6][4];
#pragma unroll
            for (int ncp = 0; ncp < 6; ncp++) {
                float p0[4] = {0.f, 0.f, 0.f, 0.f};
                float p1[4] = {0.f, 0.f, 0.f, 0.f};
#pragma unroll
                for (int kc2 = 0; kc2 < 8; kc2++) {
                    uint32_t b0, b1, b2, b3;
                    uint32_t base = sbV + (uint32_t)(kc2 * 12 + 2 * ncp) * 512;
                    lds128(b0, b1, b2, b3, base);
                    mma_bf16(p0[0], p0[1], p0[2], p0[3],
                             af[2 * kc2][0], af[2 * kc2][1],
                             af[2 * kc2][2], af[2 * kc2][3], b0, b1);
                    mma_bf16(p0[0], p0[1], p0[2], p0[3],
                             af[2 * kc2 + 1][0], af[2 * kc2 + 1][1],
                             af[2 * kc2 + 1][2], af[2 * kc2 + 1][3], b2, b3);
                    lds128(b0, b1, b2, b3, base + 512);
                    mma_bf16(p1[0], p1[1], p1[2], p1[3],
                             af[2 * kc2][0], af[2 * kc2][1],
                             af[2 * kc2][2], af[2 * kc2][3], b0, b1);
                    mma_bf16(p1[0], p1[1], p1[2], p1[3],
                             af[2 * kc2 + 1][0], af[2 * kc2 + 1][1],
                             af[2 * kc2 + 1][2], af[2 * kc2 + 1][3], b2, b3);
                }
                paf[ncp][0] = packbf(p0[0] * av0[ncp], p0[1] * av0[ncp]);
                paf[ncp][1] = packbf(p0[2] * av1[ncp], p0[3] * av1[ncp]);
                paf[ncp][2] = packbf(p1[0] * av0[ncp], p1[1] * av0[ncp]);
                paf[ncp][3] = packbf(p1[2] * av1[ncp], p1[3] * av1[ncp]);
            }

            // ---- U-GEMM: acc += pa @ (P*dt*Uhat)^T ----
#pragma unroll
            for (int i = 0; i < 96; i++) {
                uint32_t b0, b1, b2, b3;
                lds128(b0, b1, b2, b3, sbU + (uint32_t)i * 512);
                int kc2 = i >> 5, nc = i & 31;
                mma_bf16(acc[nc][0], acc[nc][1], acc[nc][2], acc[nc][3],
                         paf[2 * kc2][0], paf[2 * kc2][1],
                         paf[2 * kc2][2], paf[2 * kc2][3], b0, b1);
                mma_bf16(acc[nc][0], acc[nc][1], acc[nc][2], acc[nc][3],
                         paf[2 * kc2 + 1][0], paf[2 * kc2 + 1][1],
                         paf[2 * kc2 + 1][2], paf[2 * kc2 + 1][3], b2, b3);
            }
        }

        float2* o0 = reinterpret_cast<float2*>(out + (size_t)r0 * M_DIM);
        float2* o1 = reinterpret_cast<float2*>(out + (size_t)(r0 + 8) * M_DIM);
#pragma unroll
        for (int nc = 0; nc < 32; nc++) {
            o0[4 * nc + tig] = make_float2(acc[nc][0], acc[nc][1]);
            o1[4 * nc + tig] = make_float2(acc[nc][2], acc[nc][3]);
        }
    }
}

// ============================================================================
// kernel_launch — graph-capturable: kernel launches only, no sync, no alloc.
// ============================================================================
extern "C" void kernel_launch(void* const* d_in, const int* in_sizes, int n_in,
                              void* d_out, int out_size) {
    const float* z  = (const float*)d_in[0];
    const float* a  = (const float*)d_in[1];
    const float* A  = (const float*)d_in[2];
    const float* BU = (const float*)d_in[3];
    const float* BV = (const float*)d_in[4];
    const int* steps = (n_in > 5) ? (const int*)d_in[5] : nullptr;

    int n_rows  = in_sizes[0] / M_DIM;
    int n_tiles = n_rows / TILE_M;

    cudaFuncSetAttribute(koop_main, cudaFuncAttributeMaxDynamicSharedMemorySize,
                         W_TOTAL);

    // Precompute: init -> X2 -> {X4, T} -> {X8, Uh, Vh} -> frag
    koop_init<<<256, 256>>>(A, BU, BV);
    koop_gemm2<<<dim3(8, 8, 1), 256>>>(0, steps);
    koop_gemm2<<<dim3(8, 8, 2), 256>>>(1, steps);
    koop_gemm2<<<dim3(8, 8, 3), 256>>>(3, steps);
    koop_frag<<<(W_TOTAL / 4 + 255) / 256, 256>>>(steps);

    int dev = 0, sm_count = 0;
    cudaGetDevice(&dev);
    cudaDeviceGetAttribute(&sm_count, cudaDevAttrMultiProcessorCount, dev);
    if (sm_count <= 0) sm_count = 148;
    int grid = n_tiles < sm_count ? n_tiles : sm_count;

    koop_main<<<grid, 256, W_TOTAL>>>(z, a, steps, (float*)d_out, n_tiles);
}